// round 17
// baseline (speedup 1.0000x reference)
#include <cuda_runtime.h>
#include <cstdint>

// Problem constants
#define BB 64
#define TT 2048
#define II 64
#define HH 128
#define CH 32            // timesteps per chunk
#define NCH (TT / CH)    // 64 chunks

// Producer->consumer chunk flags. Zero-initialized at module load; consumers
// reset their batch's flags after use -> replay-safe.
__device__ int g_flags[BB][NCH];

// ---------- packed f32x2 / fast-math helpers ----------
__device__ __forceinline__ unsigned long long ffma2(unsigned long long a,
                                                    unsigned long long b,
                                                    unsigned long long c) {
    unsigned long long d;
    asm("fma.rn.f32x2 %0, %1, %2, %3;" : "=l"(d) : "l"(a), "l"(b), "l"(c));
    return d;
}
__device__ __forceinline__ unsigned long long fadd2(unsigned long long a,
                                                    unsigned long long b) {
    unsigned long long d;
    asm("add.rn.f32x2 %0, %1, %2;" : "=l"(d) : "l"(a), "l"(b));
    return d;
}
__device__ __forceinline__ float2 unpack2(unsigned long long v) {
    float2 f;
    asm("mov.b64 {%0, %1}, %2;" : "=f"(f.x), "=f"(f.y) : "l"(v));
    return f;
}
__device__ __forceinline__ float tanh_fast(float x) {
    float y;
    asm("tanh.approx.f32 %0, %1;" : "=f"(y) : "f"(x));
    return y;
}
__device__ __forceinline__ int ld_acquire(const int* p) {
    int v;
    asm volatile("ld.global.acquire.gpu.b32 %0, [%1];" : "=r"(v) : "l"(p) : "memory");
    return v;
}
__device__ __forceinline__ void st_release(int* p, int v) {
    asm volatile("st.global.release.gpu.b32 [%0], %1;" :: "l"(p), "r"(v) : "memory");
}

// ============================================================================
// grid = 128 x 256, 64 KB dynamic smem.
//  blocks [0,64):  PRODUCER for batch b: xw = Wx+bias into out in-place,
//    per-chunk (32 steps) release flags. Uses first 16KB of smem for x tiles.
//  blocks [64,128): CONSUMER for batch b-64, warp-specialized:
//    warps 0-3 = HELPERS: flag waits, LDG xw chunk -> smem, LDS h -> STG out.
//    warps 4-7 = RECURRENCE: per step 1 LDS.32 (xw) + 16 LDS.128 (h bcast) +
//      64 FFMA2 + tanh + STS + bar.sync(1,128). No global ops, no flags.
//  smem layout: [0,32K) h ring (64 slots x 128 f), [32K,64K) xw (64 slots).
// ============================================================================
__global__ __launch_bounds__(256, 1) void rnn_split_kernel(
    const float* __restrict__ x,
    const float* __restrict__ h0,
    const float* __restrict__ W,
    const float* __restrict__ U,
    const float* __restrict__ b_ih,
    const float* __restrict__ b_hh,
    float* __restrict__ out)
{
    extern __shared__ __align__(16) float sh[];
    float (*ring)[HH] = (float (*)[HH])sh;             // 64 x 128 floats
    float (*xw_s)[HH] = (float (*)[HH])(sh + 64 * HH); // 64 x 128 floats
    const int tid = threadIdx.x;

    if (blockIdx.x < BB) {
        // ==================== PRODUCER ====================
        const int b    = blockIdx.x;
        const int i    = tid & 127;
        const int half = tid >> 7;
        float (*xs2)[CH][II] = (float (*)[CH][II])sh;  // 2 x 32 x 64 = 16KB

        unsigned long long w[32];
        const ulonglong2* Wrow = (const ulonglong2*)(W + i * II);
#pragma unroll
        for (int k = 0; k < 16; k++) {
            ulonglong2 t = Wrow[k];
            w[2 * k]     = t.x;
            w[2 * k + 1] = t.y;
        }
        const float bias = b_ih[i] + b_hh[i];

        const float4* xg = (const float4*)(x + (size_t)b * TT * II);
        float* ob = out + (size_t)b * TT * HH;

        // stage chunk 0: 512 float4, 2 per thread
        const int r0 = (tid * 2) >> 4, c0 = (tid * 2) & 15;
        const int r1 = (tid * 2 + 1) >> 4, c1 = (tid * 2 + 1) & 15;
        ((float4*)xs2[0][r0])[c0] = xg[(size_t)r0 * 16 + c0];
        ((float4*)xs2[0][r1])[c1] = xg[(size_t)r1 * 16 + c1];
        __syncthreads();

#pragma unroll 1
        for (int k = 0; k < NCH; k++) {
            const int buf = k & 1;
            if (k + 1 < NCH) {
                ((float4*)xs2[buf ^ 1][r0])[c0] =
                    xg[((size_t)(k + 1) * CH + r0) * 16 + c0];
                ((float4*)xs2[buf ^ 1][r1])[c1] =
                    xg[((size_t)(k + 1) * CH + r1) * 16 + c1];
            }

#pragma unroll 1
            for (int s = 0; s < CH / 2; s++) {
                const int row = half * (CH / 2) + s;
                const ulonglong2* xv = (const ulonglong2*)xs2[buf][row];
                unsigned long long a0 = 0ull, a1 = 0ull, a2 = 0ull, a3 = 0ull;
#pragma unroll
                for (int kk = 0; kk < 16; kk += 2) {
                    ulonglong2 hA = xv[kk];
                    ulonglong2 hB = xv[kk + 1];
                    a0 = ffma2(w[2 * kk],     hA.x, a0);
                    a1 = ffma2(w[2 * kk + 1], hA.y, a1);
                    a2 = ffma2(w[2 * kk + 2], hB.x, a2);
                    a3 = ffma2(w[2 * kk + 3], hB.y, a3);
                }
                unsigned long long sm = fadd2(fadd2(a0, a1), fadd2(a2, a3));
                float2 f = unpack2(sm);
                ob[(size_t)(k * CH + row) * HH + i] = f.x + f.y + bias;
            }

            __threadfence();
            __syncthreads();
            if (tid == 0) st_release(&g_flags[b][k], 1);
        }
        return;
    }

    // ==================== CONSUMER BLOCK ====================
    const int b = blockIdx.x - BB;
    const bool is_rec = (tid >= 128);     // warps 4-7: recurrence
    const int i = tid & 127;
    float* ob = out + (size_t)b * TT * HH;

    unsigned long long u[64];
    if (is_rec) {
        const ulonglong2* Urow = (const ulonglong2*)(U + i * HH);
#pragma unroll
        for (int k = 0; k < 32; k++) {
            ulonglong2 t = Urow[k];
            u[2 * k]     = t.x;
            u[2 * k + 1] = t.y;
        }
        ring[2 * CH - 1][i] = h0[b * HH + i];   // h_{-1} in slot 63
    } else {
        // helpers: wait for chunk 0 and stage it into xw buf 0
        while (ld_acquire(&g_flags[b][0]) != 1) __nanosleep(64);
        const float4* src = (const float4*)ob;          // chunk 0 = out[0..32)
        float4*       dst = (float4*)&xw_s[0][0];       // 1024 float4
#pragma unroll
        for (int j = 0; j < 8; j++) dst[i + 128 * j] = src[i + 128 * j];
    }

    float v = 0.f;

#pragma unroll 1
    for (int k = 0; k < NCH; k++) {
        __syncthreads();   // xw chunk k staged; h chunk k-1 final; bufs swap
        const int half = k & 1;

        if (is_rec) {
#pragma unroll
            for (int s = 0; s < CH; s++) {
                const ulonglong2* hv = (const ulonglong2*)(
                    (s == 0) ? ring[(half ^ 1) * CH + (CH - 1)]
                             : ring[half * CH + s - 1]);

                // xw via one LDS.32, latency hidden under the FFMA window
                const float xwv = xw_s[half * CH + s][i];

                unsigned long long acc0 = 0ull, acc1 = 0ull;
#pragma unroll
                for (int kk = 0; kk < 32; kk++) {
                    ulonglong2 hA = hv[kk];
                    acc0 = ffma2(u[2 * kk],     hA.x, acc0);
                    acc1 = ffma2(u[2 * kk + 1], hA.y, acc1);
                }
                float2 f = unpack2(fadd2(acc0, acc1));

                float vv = tanh_fast((f.x + f.y) + xwv);
                v = vv;
                ring[half * CH + s][i] = vv;      // publish h_t (STS only)

                if (s < CH - 1)
                    asm volatile("bar.sync 1, 128;" ::: "memory");
                // s == CH-1: covered by loop-top __syncthreads
            }
        } else {
            // ---- helpers: all global traffic, big slack ----
            if (k + 1 < NCH) {
                while (ld_acquire(&g_flags[b][k + 1]) != 1) __nanosleep(64);
                const float4* src = (const float4*)(ob + (size_t)(k + 1) * CH * HH);
                float4*       dst = (float4*)&xw_s[(half ^ 1) * CH][0];
#pragma unroll
                for (int j = 0; j < 8; j++) dst[i + 128 * j] = src[i + 128 * j];
            }
            if (k > 0) {
                const float4* src = (const float4*)&ring[(half ^ 1) * CH][0];
                float4*       dst = (float4*)(ob + (size_t)(k - 1) * CH * HH);
#pragma unroll
                for (int j = 0; j < 8; j++) dst[i + 128 * j] = src[i + 128 * j];
            }
        }
    }

    __syncthreads();   // last chunk's h final in ring

    if (is_rec) {
        out[(size_t)BB * TT * HH + b * HH + i] = v;   // h_last
    } else {
        const int half = (NCH - 1) & 1;
        const float4* src = (const float4*)&ring[half * CH][0];
        float4*       dst = (float4*)(ob + (size_t)(NCH - 1) * CH * HH);
#pragma unroll
        for (int j = 0; j < 8; j++) dst[i + 128 * j] = src[i + 128 * j];
        if (i < NCH) g_flags[b][i] = 0;   // reset flags for next launch/replay
    }
}

// ============================================================================
// Launch
// ============================================================================
extern "C" void kernel_launch(void* const* d_in, const int* in_sizes, int n_in,
                              void* d_out, int out_size)
{
    (void)in_sizes; (void)n_in; (void)out_size;
    const float* x    = (const float*)d_in[0];
    const float* h0   = (const float*)d_in[1];
    const float* W    = (const float*)d_in[2];
    const float* U    = (const float*)d_in[3];
    const float* b_ih = (const float*)d_in[4];
    const float* b_hh = (const float*)d_in[5];
    float* out = (float*)d_out;

    const int smem = 64 * HH * 4 * 2;   // 64 KB
    cudaFuncSetAttribute(rnn_split_kernel,
                         cudaFuncAttributeMaxDynamicSharedMemorySize, smem);
    rnn_split_kernel<<<2 * BB, 256, smem>>>(x, h0, W, U, b_ih, b_hh, out);
}